// round 3
// baseline (speedup 1.0000x reference)
#include <cuda_runtime.h>
#include <math.h>

#define Bn 4
#define Cn 32
#define HF 256
#define WF 256
#define N0 (4*32*256*256)
#define N1 (4*32*128*128)
#define N2 (4*32*64*64)

// ---------------- device scratch (static allocation: allowed) ----------------
__device__ float g_s1[N1];
__device__ float g_s2[N2];
__device__ float g_z0[N0];
__device__ float g_q [N0];
__device__ float g_z1[N1];
__device__ float g_z2[N2];
__device__ float g_y1[N0];
__device__ float g_y2[N0];
__device__ float g_part[3*128*8];
__device__ float g_alpha[12];

// ---------------- avg pool 2x2 ----------------
__global__ void pool_kernel(const float* __restrict__ src, float* __restrict__ dst, int Hs, int Ws)
{
    int Hd = Hs >> 1, Wd = Ws >> 1;
    int total = Bn*Cn*Hd*Wd;
    int idx = blockIdx.x*blockDim.x + threadIdx.x;
    if (idx >= total) return;
    int x = idx % Wd; int y = (idx/Wd) % Hd; int bc = idx/(Wd*Hd);
    const float* p = src + (bc*Hs + 2*y)*Ws + 2*x;
    dst[idx] = 0.25f*(p[0] + p[1] + p[Ws] + p[Ws+1]);
}

// ---------------- fused dwconv3 + pw1x1 + BN + SiLU (+ optional q-proj) ----------------
template<int H, int W, bool FUSEQ>
__global__ void ds_kernel(const float* __restrict__ x,
                          const float* __restrict__ dw,
                          const float* __restrict__ pw,
                          const float* __restrict__ gg,
                          const float* __restrict__ bb,
                          const float* __restrict__ mm,
                          const float* __restrict__ vv,
                          const float* __restrict__ qw,
                          float* __restrict__ z, float* __restrict__ q)
{
    __shared__ float smem[10368 + 320];   // 42.75 KB static
    float* s_tile = smem;                 // 32 * 18 * 18
    float* s_dw   = smem + 10368;         // 288
    int tid = threadIdx.x;
    int tx = tid & 15, ty = tid >> 4;
    int bx = blockIdx.x * 16, by = blockIdx.y * 16;
    int b  = blockIdx.z;
    const float* xb = x + b*Cn*H*W;

    for (int i = tid; i < 32*324; i += 256) {
        int c = i / 324; int r = i % 324; int yy = r/18, xx = r%18;
        int gy = by + yy - 1, gx = bx + xx - 1;
        float val = 0.f;
        if (gy >= 0 && gy < H && gx >= 0 && gx < W) val = xb[(c*H+gy)*W + gx];
        s_tile[i] = val;
    }
    for (int i = tid; i < 288; i += 256) s_dw[i] = dw[i];
    __syncthreads();

    float t[32];
    #pragma unroll
    for (int c = 0; c < 32; c++) {
        const float* tp = s_tile + c*324 + ty*18 + tx;
        const float* wp = s_dw + c*9;
        float a = 0.f;
        #pragma unroll
        for (int ky = 0; ky < 3; ky++)
            #pragma unroll
            for (int kx = 0; kx < 3; kx++)
                a += tp[ky*18+kx]*wp[ky*3+kx];
        t[c] = a;
    }
    __syncthreads();   // tile region is dead; reuse it for weights

    float* s_pw = smem;
    float* s_qw = smem + 1024;
    float* s_sc = smem + 2048;
    float* s_bi = smem + 2080;
    for (int i = tid; i < 1024; i += 256) s_pw[i] = pw[i];
    if (FUSEQ) for (int i = tid; i < 1024; i += 256) s_qw[i] = qw[i];
    if (tid < 32) {
        float sc = gg[tid] * rsqrtf(vv[tid] + 1e-5f);
        s_sc[tid] = sc; s_bi[tid] = bb[tid] - mm[tid]*sc;
    }
    __syncthreads();

    int gy = by + ty, gx = bx + tx;
    float* zp = z + (b*Cn*H + gy)*W + gx;
    float zl[32];
    #pragma unroll
    for (int o = 0; o < 32; o++) {
        float a = 0.f;
        #pragma unroll
        for (int c = 0; c < 32; c++) a += s_pw[o*32+c]*t[c];
        float vbn = a*s_sc[o] + s_bi[o];
        float sg = 1.f/(1.f + __expf(-vbn));
        float zz = vbn*sg;
        zl[o] = zz;
        zp[o*H*W] = zz;
    }
    if (FUSEQ) {
        float* qp = q + (b*Cn*H + gy)*W + gx;
        #pragma unroll
        for (int o = 0; o < 32; o++) {
            float a = 0.f;
            #pragma unroll
            for (int c = 0; c < 32; c++) a += s_qw[o*32+c]*zl[c];
            qp[o*H*W] = a;
        }
    }
}

// ---------------- fused offset head: conv3x3 + SiLU + conv1x1 + tanh/softmax + deform sample ----------------
template<int Hc, int Wc>
__global__ void head_kernel(const float* __restrict__ q,
                            const float* __restrict__ zc,
                            const float* __restrict__ w1,
                            const float* __restrict__ w2,
                            const float* __restrict__ b2,
                            float* __restrict__ y)
{
    __shared__ float s_tile[16*324];  // 16 channels x 18x18
    __shared__ float s_w1[2304];      // 16 out x 16 in x 9
    __shared__ float s_w2[192];
    __shared__ float s_b2[12];
    int tid = threadIdx.x;
    int tx = tid & 15, ty = tid >> 4;
    int bx = blockIdx.x*16, by = blockIdx.y*16;
    int b  = blockIdx.z;

    if (tid < 192) s_w2[tid] = w2[tid];
    else if (tid < 204) s_b2[tid-192] = b2[tid-192];

    float h[16];
    #pragma unroll
    for (int o = 0; o < 16; o++) h[o] = 0.f;

    const float* qb = q + b*32*65536;
    for (int cg = 0; cg < 2; cg++) {
        __syncthreads();
        for (int i = tid; i < 16*324; i += 256) {
            int c = i/324; int r = i%324; int yy = r/18, xx = r%18;
            int gy = by+yy-1, gx = bx+xx-1;
            float val = 0.f;
            if (gy >= 0 && gy < 256 && gx >= 0 && gx < 256)
                val = qb[((cg*16+c)*256+gy)*256+gx];
            s_tile[i] = val;
        }
        for (int i = tid; i < 2304; i += 256) {
            int o = i / 144; int rem = i % 144; int cl = rem/9; int kk = rem%9;
            s_w1[i] = w1[(o*32 + cg*16 + cl)*9 + kk];
        }
        __syncthreads();
        #pragma unroll
        for (int cl = 0; cl < 16; cl++) {
            float v[9];
            const float* tp = s_tile + cl*324 + ty*18 + tx;
            #pragma unroll
            for (int ky = 0; ky < 3; ky++)
                #pragma unroll
                for (int kx = 0; kx < 3; kx++) v[ky*3+kx] = tp[ky*18+kx];
            const float* wp = s_w1 + cl*9;
            #pragma unroll
            for (int o = 0; o < 16; o++) {
                const float* w = wp + o*144;
                float a = h[o];
                #pragma unroll
                for (int kk = 0; kk < 9; kk++) a += w[kk]*v[kk];
                h[o] = a;
            }
        }
    }

    #pragma unroll
    for (int o = 0; o < 16; o++) { float sg = 1.f/(1.f+__expf(-h[o])); h[o] *= sg; }

    float out[12];
    #pragma unroll
    for (int o = 0; o < 12; o++) {
        float a = s_b2[o];
        #pragma unroll
        for (int i = 0; i < 16; i++) a += s_w2[o*16+i]*h[i];
        out[o] = a;
    }

    // softmax over the 4 attention logits (channels 8..11)
    float mlog = fmaxf(fmaxf(out[8],out[9]), fmaxf(out[10],out[11]));
    float e[4]; float es = 0.f;
    #pragma unroll
    for (int k = 0; k < 4; k++) { e[k] = __expf(out[8+k]-mlog); es += e[k]; }
    float inv = 1.f/es;

    int gy = by+ty, gx = bx+tx;
    // base grid collapses to: ix = clip(xc + R_MAX*tanh(offx), 0, Wc-1)
    float xc = (gx+0.5f)*((float)Wc/256.f) - 0.5f;
    float yc = (gy+0.5f)*((float)Hc/256.f) - 0.5f;

    float yacc[32];
    #pragma unroll
    for (int c = 0; c < 32; c++) yacc[c] = 0.f;
    const float* zb = zc + b*32*Hc*Wc;

    #pragma unroll
    for (int k = 0; k < 4; k++) {
        float wk = e[k]*inv;
        float ix = xc + 2.0f*tanhf(out[2*k]);
        float iy = yc + 2.0f*tanhf(out[2*k+1]);
        ix = fminf(fmaxf(ix, 0.f), (float)(Wc-1));
        iy = fminf(fmaxf(iy, 0.f), (float)(Hc-1));
        float x0 = floorf(ix), y0 = floorf(iy);
        float wx = ix-x0, wy = iy-y0;
        int x0i = (int)x0, y0i = (int)y0;
        int x1i = min(x0i+1, Wc-1), y1i = min(y0i+1, Hc-1);
        float w00 = wk*(1.f-wx)*(1.f-wy), w01 = wk*wx*(1.f-wy);
        float w10 = wk*(1.f-wx)*wy,       w11 = wk*wx*wy;
        int i00 = y0i*Wc+x0i, i01 = y0i*Wc+x1i, i10 = y1i*Wc+x0i, i11 = y1i*Wc+x1i;
        #pragma unroll
        for (int c = 0; c < 32; c++) {
            const float* p = zb + c*Hc*Wc;
            yacc[c] += w00*__ldg(p+i00) + w01*__ldg(p+i01)
                     + w10*__ldg(p+i10) + w11*__ldg(p+i11);
        }
    }
    float* yp = y + (b*32*256 + gy)*256 + gx;
    #pragma unroll
    for (int c = 0; c < 32; c++) yp[c*65536] = yacc[c];
}

// ---------------- deterministic partial-sum reduction for channel means ----------------
__global__ void reduce_kernel(const float* __restrict__ z0,
                              const float* __restrict__ y1,
                              const float* __restrict__ y2,
                              float* __restrict__ part)
{
    int chunk = blockIdx.x;   // 0..7
    int bc    = blockIdx.y;   // 0..127
    int arr   = blockIdx.z;   // 0..2
    const float* src = (arr==0) ? z0 : ((arr==1) ? y1 : y2);
    const float* p = src + bc*65536 + chunk*8192;
    float s = 0.f;
    for (int i = threadIdx.x; i < 8192; i += 256) s += p[i];
    __shared__ float sm[256];
    sm[threadIdx.x] = s; __syncthreads();
    for (int o = 128; o > 0; o >>= 1) {
        if (threadIdx.x < o) sm[threadIdx.x] += sm[threadIdx.x+o];
        __syncthreads();
    }
    if (threadIdx.x == 0) part[(arr*128+bc)*8 + chunk] = sm[0];
}

// ---------------- gating MLP -> alpha ----------------
__global__ void alpha_kernel(const float* __restrict__ part,
                             const float* __restrict__ rw1, const float* __restrict__ rb1,
                             const float* __restrict__ rw2, const float* __restrict__ rb2,
                             float* __restrict__ alpha)
{
    __shared__ float s_cat[4*96];
    int tid = threadIdx.x;  // 128
    {
        int b = tid >> 5, c = tid & 31;
        int bc = b*32 + c;
        for (int arr = 0; arr < 3; arr++) {
            float s = 0.f;
            for (int k = 0; k < 8; k++) s += part[(arr*128+bc)*8 + k];
            s_cat[b*96 + arr*32 + c] = s * (1.0f/65536.0f);
        }
    }
    __syncthreads();
    if (tid < 4) {
        int b = tid;
        float hid[32];
        for (int o = 0; o < 32; o++) {
            float a = rb1[o];
            for (int j = 0; j < 96; j++) a += s_cat[b*96+j]*rw1[j*32+o];
            float sg = 1.f/(1.f + __expf(-a));
            hid[o] = a*sg;
        }
        float lg[3];
        for (int t2 = 0; t2 < 3; t2++) {
            float a = rb2[t2];
            for (int o = 0; o < 32; o++) a += hid[o]*rw2[o*3+t2];
            lg[t2] = a;
        }
        float m = fmaxf(lg[0], fmaxf(lg[1], lg[2]));
        float e0 = __expf(lg[0]-m), e1 = __expf(lg[1]-m), e2 = __expf(lg[2]-m);
        float inv = 1.f/(e0+e1+e2);
        alpha[b*3+0] = e0*inv; alpha[b*3+1] = e1*inv; alpha[b*3+2] = e2*inv;
    }
}

// ---------------- final: alpha-mix + 1x1 conv + residual ----------------
__global__ void final_kernel(const float* __restrict__ x,
                             const float* __restrict__ z0,
                             const float* __restrict__ y1,
                             const float* __restrict__ y2,
                             const float* __restrict__ fw,
                             const float* __restrict__ alpha,
                             float* __restrict__ out)
{
    __shared__ float s_fw[1024];
    for (int i = threadIdx.x; i < 1024; i += 256) s_fw[i] = fw[i];
    __syncthreads();
    int b = blockIdx.y;
    int pix = blockIdx.x*256 + threadIdx.x;
    float a0 = alpha[b*3], a1 = alpha[b*3+1], a2 = alpha[b*3+2];
    int base = b*32*65536 + pix;
    float mix[32];
    #pragma unroll
    for (int c = 0; c < 32; c++) {
        int idx = base + c*65536;
        mix[c] = a0*z0[idx] + a1*y1[idx] + a2*y2[idx];
    }
    #pragma unroll
    for (int o = 0; o < 32; o++) {
        float a = 0.f;
        #pragma unroll
        for (int c = 0; c < 32; c++) a += s_fw[o*32+c]*mix[c];
        int idx = base + o*65536;
        out[idx] = x[idx] + a;
    }
}

// ---------------- launch ----------------
extern "C" void kernel_launch(void* const* d_in, const int* in_sizes, int n_in,
                              void* d_out, int out_size)
{
    const float* x       = (const float*)d_in[0];
    const float* ds0_dw  = (const float*)d_in[1];
    const float* ds0_pw  = (const float*)d_in[2];
    const float* ds0_g   = (const float*)d_in[3];
    const float* ds0_b   = (const float*)d_in[4];
    const float* ds0_m   = (const float*)d_in[5];
    const float* ds0_v   = (const float*)d_in[6];
    const float* ds1_dw  = (const float*)d_in[7];
    const float* ds1_pw  = (const float*)d_in[8];
    const float* ds1_g   = (const float*)d_in[9];
    const float* ds1_b   = (const float*)d_in[10];
    const float* ds1_m   = (const float*)d_in[11];
    const float* ds1_v   = (const float*)d_in[12];
    const float* ds2_dw  = (const float*)d_in[13];
    const float* ds2_pw  = (const float*)d_in[14];
    const float* ds2_g   = (const float*)d_in[15];
    const float* ds2_b   = (const float*)d_in[16];
    const float* ds2_m   = (const float*)d_in[17];
    const float* ds2_v   = (const float*)d_in[18];
    const float* qproj_w = (const float*)d_in[19];
    const float* h1_w1   = (const float*)d_in[20];
    const float* h1_w2   = (const float*)d_in[21];
    const float* h1_b2   = (const float*)d_in[22];
    const float* h2_w1   = (const float*)d_in[23];
    const float* h2_w2   = (const float*)d_in[24];
    const float* h2_b2   = (const float*)d_in[25];
    const float* r_w1    = (const float*)d_in[26];
    const float* r_b1    = (const float*)d_in[27];
    const float* r_w2    = (const float*)d_in[28];
    const float* r_b2    = (const float*)d_in[29];
    const float* final_w = (const float*)d_in[30];
    float* out = (float*)d_out;

    float *s1, *s2, *z0, *q, *z1, *z2, *y1, *y2, *part, *alpha;
    cudaGetSymbolAddress((void**)&s1,    g_s1);
    cudaGetSymbolAddress((void**)&s2,    g_s2);
    cudaGetSymbolAddress((void**)&z0,    g_z0);
    cudaGetSymbolAddress((void**)&q,     g_q);
    cudaGetSymbolAddress((void**)&z1,    g_z1);
    cudaGetSymbolAddress((void**)&z2,    g_z2);
    cudaGetSymbolAddress((void**)&y1,    g_y1);
    cudaGetSymbolAddress((void**)&y2,    g_y2);
    cudaGetSymbolAddress((void**)&part,  g_part);
    cudaGetSymbolAddress((void**)&alpha, g_alpha);

    pool_kernel<<<(N1+255)/256, 256>>>(x,  s1, 256, 256);
    pool_kernel<<<(N2+255)/256, 256>>>(s1, s2, 128, 128);

    ds_kernel<256,256,true ><<<dim3(16,16,4), 256>>>(x,  ds0_dw, ds0_pw, ds0_g, ds0_b, ds0_m, ds0_v, qproj_w, z0, q);
    ds_kernel<128,128,false><<<dim3( 8, 8,4), 256>>>(s1, ds1_dw, ds1_pw, ds1_g, ds1_b, ds1_m, ds1_v, nullptr, z1, nullptr);
    ds_kernel< 64, 64,false><<<dim3( 4, 4,4), 256>>>(s2, ds2_dw, ds2_pw, ds2_g, ds2_b, ds2_m, ds2_v, nullptr, z2, nullptr);

    head_kernel<128,128><<<dim3(16,16,4), 256>>>(q, z1, h1_w1, h1_w2, h1_b2, y1);
    head_kernel< 64, 64><<<dim3(16,16,4), 256>>>(q, z2, h2_w1, h2_w2, h2_b2, y2);

    reduce_kernel<<<dim3(8,128,3), 256>>>(z0, y1, y2, part);
    alpha_kernel<<<1, 128>>>(part, r_w1, r_b1, r_w2, r_b2, alpha);

    final_kernel<<<dim3(256,4), 256>>>(x, z0, y1, y2, final_w, alpha, out);
}

// round 4
// speedup vs baseline: 1.4025x; 1.4025x over previous
#include <cuda_runtime.h>
#include <math.h>

#define Bn 4
#define Cn 32
#define N0 (4*32*256*256)
#define N1 (4*32*128*128)
#define N2 (4*32*64*64)

// ---------------- device scratch ----------------
__device__ float g_z0[N0];
__device__ float g_q [N0];
__device__ float g_z1[N1];   // HWC layout: (B,H,W,C)
__device__ float g_z2[N2];   // HWC layout
__device__ float g_y1[N0];   // CHW
__device__ float g_y2[N0];   // CHW
__device__ float g_part[3*128*8];
__device__ float g_alpha[12];

// ---------------- fused (inline-pool) + dwconv3 + pw1x1 + BN + SiLU (+ q-proj) ----------------
// F = pooling factor from full-res x. HWC selects output layout.
template<int H, int W, int F, bool FUSEQ, bool HWC>
__device__ __forceinline__ void ds_impl(float* smem,
                          const float* __restrict__ x,
                          const float* __restrict__ dw,
                          const float* __restrict__ pw,
                          const float* __restrict__ gg,
                          const float* __restrict__ bb,
                          const float* __restrict__ mm,
                          const float* __restrict__ vv,
                          const float* __restrict__ qw,
                          float* __restrict__ z, float* __restrict__ q,
                          int bxi, int byi, int b)
{
    float* s_tile = smem;            // 32*324
    float* s_dw   = smem + 10368;    // 288
    int tid = threadIdx.x;
    int tx = tid & 15, ty = tid >> 4;
    int bx = bxi * 16, by = byi * 16;
    const float* xb = x + b*Cn*256*256;

    for (int i = tid; i < 32*324; i += 256) {
        int c = i / 324; int r = i % 324; int yy = r/18, xx = r%18;
        int gy = by + yy - 1, gx = bx + xx - 1;
        float val = 0.f;
        if (gy >= 0 && gy < H && gx >= 0 && gx < W) {
            if (F == 1) {
                val = xb[(c*256+gy)*256 + gx];
            } else if (F == 2) {
                const float2* p = (const float2*)(xb + (c*256 + 2*gy)*256 + 2*gx);
                float2 a = p[0], bq = p[128];
                val = 0.25f*(a.x + a.y + bq.x + bq.y);
            } else {
                const float4* p = (const float4*)(xb + (c*256 + 4*gy)*256 + 4*gx);
                float s = 0.f;
                #pragma unroll
                for (int fy = 0; fy < 4; fy++) {
                    float4 v4 = p[fy*64];
                    s += v4.x + v4.y + v4.z + v4.w;
                }
                val = s * 0.0625f;
            }
        }
        s_tile[i] = val;
    }
    for (int i = tid; i < 288; i += 256) s_dw[i] = dw[i];
    __syncthreads();

    float t[32];
    #pragma unroll
    for (int c = 0; c < 32; c++) {
        const float* tp = s_tile + c*324 + ty*18 + tx;
        const float* wp = s_dw + c*9;
        float a = 0.f;
        #pragma unroll
        for (int ky = 0; ky < 3; ky++)
            #pragma unroll
            for (int kx = 0; kx < 3; kx++)
                a += tp[ky*18+kx]*wp[ky*3+kx];
        t[c] = a;
    }
    __syncthreads();   // tile region dead; reuse for weights

    float* s_pw = smem;
    float* s_qw = smem + 1024;
    float* s_sc = smem + 2048;
    float* s_bi = smem + 2080;
    for (int i = tid; i < 1024; i += 256) s_pw[i] = pw[i];
    if (FUSEQ) for (int i = tid; i < 1024; i += 256) s_qw[i] = qw[i];
    if (tid < 32) {
        float sc = gg[tid] * rsqrtf(vv[tid] + 1e-5f);
        s_sc[tid] = sc; s_bi[tid] = bb[tid] - mm[tid]*sc;
    }
    __syncthreads();

    int gy = by + ty, gx = bx + tx;
    float zl[32];
    #pragma unroll
    for (int o = 0; o < 32; o++) {
        float a = 0.f;
        #pragma unroll
        for (int c = 0; c < 32; c++) a += s_pw[o*32+c]*t[c];
        float vbn = a*s_sc[o] + s_bi[o];
        float sg = 1.f/(1.f + __expf(-vbn));
        zl[o] = vbn*sg;
    }
    if (HWC) {
        float* zp = z + ((size_t)(b*H + gy)*W + gx)*32;
        #pragma unroll
        for (int o = 0; o < 32; o++) zp[o] = zl[o];
    } else {
        float* zp = z + ((size_t)b*Cn*H + gy)*W + gx;
        #pragma unroll
        for (int o = 0; o < 32; o++) zp[o*H*W] = zl[o];
    }
    if (FUSEQ) {
        float* qp = q + ((size_t)b*Cn*H + gy)*W + gx;
        #pragma unroll
        for (int o = 0; o < 32; o++) {
            float a = 0.f;
            #pragma unroll
            for (int c = 0; c < 32; c++) a += s_qw[o*32+c]*zl[c];
            qp[o*H*W] = a;
        }
    }
}

__global__ void __launch_bounds__(256) ds_fat_kernel(
    const float* __restrict__ x,
    const float* d0dw, const float* d0pw, const float* d0g, const float* d0b, const float* d0m, const float* d0v,
    const float* d1dw, const float* d1pw, const float* d1g, const float* d1b, const float* d1m, const float* d1v,
    const float* d2dw, const float* d2pw, const float* d2g, const float* d2b, const float* d2m, const float* d2v,
    const float* qw, float* z0, float* q, float* z1, float* z2)
{
    __shared__ float smem[10688];
    int bid = blockIdx.x;
    if (bid < 256) {       // ds1: 8x8x4
        ds_impl<128,128,2,false,true>(smem, x, d1dw, d1pw, d1g, d1b, d1m, d1v, nullptr, z1, nullptr,
                                      bid & 7, (bid >> 3) & 7, bid >> 6);
    } else if (bid < 320) { // ds2: 4x4x4
        int r = bid - 256;
        ds_impl<64,64,4,false,true>(smem, x, d2dw, d2pw, d2g, d2b, d2m, d2v, nullptr, z2, nullptr,
                                    r & 3, (r >> 2) & 3, r >> 4);
    } else {               // ds0: 16x16x4
        int r = bid - 320;
        ds_impl<256,256,1,true,false>(smem, x, d0dw, d0pw, d0g, d0b, d0m, d0v, qw, z0, q,
                                      r & 15, (r >> 4) & 15, r >> 8);
    }
}

// ---------------- fused offset head (4 rows/thread) + deform sample ----------------
// smem: tile 8ch x 18 rows x pitch68 = 9792 | w1 8*16*12 = 1536 | w2 192 | b2 16
template<int Hc, int Wc>
__device__ __forceinline__ void head_impl(float* smem,
                            const float* __restrict__ q,
                            const float* __restrict__ zc,   // HWC
                            const float* __restrict__ w1,
                            const float* __restrict__ w2,
                            const float* __restrict__ b2,
                            float* __restrict__ y,
                            int bxi, int byi, int b)
{
    float* s_tile = smem;            // 9792
    float* s_w1   = smem + 9792;     // 1536
    float* s_w2   = s_w1 + 1536;     // 192
    float* s_b2   = s_w2 + 192;      // 16
    int tid = threadIdx.x;
    int tx = tid & 63;               // 64 columns
    int tyq = tid >> 6;              // 4 row-groups
    int bx = bxi*64, by = byi*16;
    int r0 = tyq*4;

    if (tid < 192) s_w2[tid] = w2[tid];
    if (tid >= 192 && tid < 204) s_b2[tid-192] = b2[tid-192];

    const float* qb = q + (size_t)b*32*65536;

    float acc[16][4];
    #pragma unroll
    for (int o = 0; o < 16; o++)
        #pragma unroll
        for (int r = 0; r < 4; r++) acc[o][r] = 0.f;

    for (int g = 0; g < 4; g++) {
        __syncthreads();
        // tile: 8 channels x 18 rows x 66 cols (pitch 68)
        for (int i = tid; i < 8*18*66; i += 256) {
            int c = i / (18*66); int r = i % (18*66); int yy = r/66, xx = r%66;
            int gy = by + yy - 1, gx = bx + xx - 1;
            float val = 0.f;
            if ((unsigned)gy < 256u && (unsigned)gx < 256u)
                val = qb[((g*8+c)*256 + gy)*256 + gx];
            s_tile[(c*18 + yy)*68 + xx] = val;
        }
        // weights: [cl][o][12] (pad to 12 for aligned vector LDS)
        for (int i = tid; i < 1536; i += 256) {
            int cl = i / 192; int o = (i / 12) % 16; int kk = i % 12;
            s_w1[i] = (kk < 9) ? w1[(o*32 + g*8 + cl)*9 + kk] : 0.f;
        }
        __syncthreads();

        #pragma unroll
        for (int cl = 0; cl < 8; cl++) {
            float vw[6][3];
            const float* tp = s_tile + cl*1224 + r0*68 + tx;
            #pragma unroll
            for (int rr = 0; rr < 6; rr++)
                #pragma unroll
                for (int cc = 0; cc < 3; cc++) vw[rr][cc] = tp[rr*68 + cc];
            const float* wbase = s_w1 + cl*192;
            #pragma unroll
            for (int o = 0; o < 16; o++) {
                float w[9];
                #pragma unroll
                for (int kk = 0; kk < 9; kk++) w[kk] = wbase[o*12 + kk];
                #pragma unroll
                for (int r = 0; r < 4; r++) {
                    float a = acc[o][r];
                    #pragma unroll
                    for (int ky = 0; ky < 3; ky++)
                        #pragma unroll
                        for (int kx = 0; kx < 3; kx++)
                            a += w[ky*3+kx]*vw[r+ky][kx];
                    acc[o][r] = a;
                }
            }
        }
    }

    // SiLU on hidden
    #pragma unroll
    for (int o = 0; o < 16; o++)
        #pragma unroll
        for (int r = 0; r < 4; r++) {
            float h = acc[o][r];
            acc[o][r] = h / (1.f + __expf(-h));
        }

    // conv1x1 to 12 outputs, all rows first (frees acc)
    float o12[4][12];
    #pragma unroll
    for (int r = 0; r < 4; r++)
        #pragma unroll
        for (int j = 0; j < 12; j++) {
            float a = s_b2[j];
            #pragma unroll
            for (int i = 0; i < 16; i++) a += s_w2[j*16+i]*acc[i][r];
            o12[r][j] = a;
        }

    const float4* zb4 = (const float4*)(zc + (size_t)b*Hc*Wc*32);
    int gx = bx + tx;
    float xc = (gx + 0.5f)*((float)Wc/256.f) - 0.5f;

    #pragma unroll
    for (int r = 0; r < 4; r++) {
        int gy = by + r0 + r;
        float yc = (gy + 0.5f)*((float)Hc/256.f) - 0.5f;
        float* op = o12[r];
        float mlog = fmaxf(fmaxf(op[8],op[9]), fmaxf(op[10],op[11]));
        float e[4]; float es = 0.f;
        #pragma unroll
        for (int k = 0; k < 4; k++) { e[k] = __expf(op[8+k]-mlog); es += e[k]; }
        float inv = 1.f/es;

        float4 yac[8];
        #pragma unroll
        for (int v = 0; v < 8; v++) yac[v] = make_float4(0.f,0.f,0.f,0.f);

        #pragma unroll
        for (int k = 0; k < 4; k++) {
            float wk = e[k]*inv;
            float ix = xc + 2.0f*tanhf(op[2*k]);
            float iy = yc + 2.0f*tanhf(op[2*k+1]);
            ix = fminf(fmaxf(ix, 0.f), (float)(Wc-1));
            iy = fminf(fmaxf(iy, 0.f), (float)(Hc-1));
            float x0 = floorf(ix), y0 = floorf(iy);
            float wx = ix-x0, wy = iy-y0;
            int x0i = (int)x0, y0i = (int)y0;
            int x1i = min(x0i+1, Wc-1), y1i = min(y0i+1, Hc-1);
            float w00 = wk*(1.f-wx)*(1.f-wy), w01 = wk*wx*(1.f-wy);
            float w10 = wk*(1.f-wx)*wy,       w11 = wk*wx*wy;
            int i00 = (y0i*Wc + x0i)*8, i01 = (y0i*Wc + x1i)*8;
            int i10 = (y1i*Wc + x0i)*8, i11 = (y1i*Wc + x1i)*8;
            #pragma unroll
            for (int v = 0; v < 8; v++) {
                float4 a00 = __ldg(zb4 + i00 + v);
                float4 a01 = __ldg(zb4 + i01 + v);
                float4 a10 = __ldg(zb4 + i10 + v);
                float4 a11 = __ldg(zb4 + i11 + v);
                yac[v].x += w00*a00.x + w01*a01.x + w10*a10.x + w11*a11.x;
                yac[v].y += w00*a00.y + w01*a01.y + w10*a10.y + w11*a11.y;
                yac[v].z += w00*a00.z + w01*a01.z + w10*a10.z + w11*a11.z;
                yac[v].w += w00*a00.w + w01*a01.w + w10*a10.w + w11*a11.w;
            }
        }
        float* yp = y + (((size_t)b*32)*256 + gy)*256 + gx;
        #pragma unroll
        for (int v = 0; v < 8; v++) {
            yp[(4*v+0)*65536] = yac[v].x;
            yp[(4*v+1)*65536] = yac[v].y;
            yp[(4*v+2)*65536] = yac[v].z;
            yp[(4*v+3)*65536] = yac[v].w;
        }
    }
}

__global__ void __launch_bounds__(256, 2) head_fat_kernel(
    const float* __restrict__ q,
    const float* __restrict__ z1, const float* __restrict__ z2,
    const float* h1w1, const float* h1w2, const float* h1b2,
    const float* h2w1, const float* h2w2, const float* h2b2,
    float* y1, float* y2)
{
    __shared__ float smem[11552];
    int hb = blockIdx.x;
    if (hb < 256) {
        head_impl<128,128>(smem, q, z1, h1w1, h1w2, h1b2, y1,
                           hb & 3, (hb >> 2) & 15, hb >> 6);
    } else {
        int r = hb - 256;
        head_impl<64,64>(smem, q, z2, h2w1, h2w2, h2b2, y2,
                         r & 3, (r >> 2) & 15, r >> 6);
    }
}

// ---------------- deterministic reduction for channel means ----------------
__global__ void reduce_kernel(const float* __restrict__ z0,
                              const float* __restrict__ y1,
                              const float* __restrict__ y2,
                              float* __restrict__ part)
{
    int chunk = blockIdx.x;   // 0..7
    int bc    = blockIdx.y;   // 0..127
    int arr   = blockIdx.z;   // 0..2
    const float* src = (arr==0) ? z0 : ((arr==1) ? y1 : y2);
    const float* p = src + (size_t)bc*65536 + chunk*8192;
    float s = 0.f;
    for (int i = threadIdx.x; i < 8192; i += 256) s += p[i];
    __shared__ float sm[256];
    sm[threadIdx.x] = s; __syncthreads();
    for (int o = 128; o > 0; o >>= 1) {
        if (threadIdx.x < o) sm[threadIdx.x] += sm[threadIdx.x+o];
        __syncthreads();
    }
    if (threadIdx.x == 0) part[(arr*128+bc)*8 + chunk] = sm[0];
}

// ---------------- gating MLP -> alpha ----------------
__global__ void alpha_kernel(const float* __restrict__ part,
                             const float* __restrict__ rw1, const float* __restrict__ rb1,
                             const float* __restrict__ rw2, const float* __restrict__ rb2,
                             float* __restrict__ alpha)
{
    __shared__ float s_cat[4*96];
    int tid = threadIdx.x;  // 128
    {
        int b = tid >> 5, c = tid & 31;
        int bc = b*32 + c;
        for (int arr = 0; arr < 3; arr++) {
            float s = 0.f;
            for (int k = 0; k < 8; k++) s += part[(arr*128+bc)*8 + k];
            s_cat[b*96 + arr*32 + c] = s * (1.0f/65536.0f);
        }
    }
    __syncthreads();
    if (tid < 4) {
        int b = tid;
        float hid[32];
        for (int o = 0; o < 32; o++) {
            float a = rb1[o];
            for (int j = 0; j < 96; j++) a += s_cat[b*96+j]*rw1[j*32+o];
            float sg = 1.f/(1.f + __expf(-a));
            hid[o] = a*sg;
        }
        float lg[3];
        for (int t2 = 0; t2 < 3; t2++) {
            float a = rb2[t2];
            for (int o = 0; o < 32; o++) a += hid[o]*rw2[o*3+t2];
            lg[t2] = a;
        }
        float m = fmaxf(lg[0], fmaxf(lg[1], lg[2]));
        float e0 = __expf(lg[0]-m), e1 = __expf(lg[1]-m), e2 = __expf(lg[2]-m);
        float inv = 1.f/(e0+e1+e2);
        alpha[b*3+0] = e0*inv; alpha[b*3+1] = e1*inv; alpha[b*3+2] = e2*inv;
    }
}

// ---------------- final: alpha-mix + 1x1 conv + residual ----------------
__global__ void final_kernel(const float* __restrict__ x,
                             const float* __restrict__ z0,
                             const float* __restrict__ y1,
                             const float* __restrict__ y2,
                             const float* __restrict__ fw,
                             const float* __restrict__ alpha,
                             float* __restrict__ out)
{
    __shared__ float s_fw[1024];
    for (int i = threadIdx.x; i < 1024; i += 256) s_fw[i] = fw[i];
    __syncthreads();
    int b = blockIdx.y;
    int pix = blockIdx.x*256 + threadIdx.x;
    float a0 = alpha[b*3], a1 = alpha[b*3+1], a2 = alpha[b*3+2];
    size_t base = (size_t)b*32*65536 + pix;
    float mix[32];
    #pragma unroll
    for (int c = 0; c < 32; c++) {
        size_t idx = base + (size_t)c*65536;
        mix[c] = a0*z0[idx] + a1*y1[idx] + a2*y2[idx];
    }
    #pragma unroll
    for (int o = 0; o < 32; o++) {
        float a = 0.f;
        #pragma unroll
        for (int c = 0; c < 32; c++) a += s_fw[o*32+c]*mix[c];
        size_t idx = base + (size_t)o*65536;
        out[idx] = x[idx] + a;
    }
}

// ---------------- launch ----------------
extern "C" void kernel_launch(void* const* d_in, const int* in_sizes, int n_in,
                              void* d_out, int out_size)
{
    const float* x       = (const float*)d_in[0];
    const float* ds0_dw  = (const float*)d_in[1];
    const float* ds0_pw  = (const float*)d_in[2];
    const float* ds0_g   = (const float*)d_in[3];
    const float* ds0_b   = (const float*)d_in[4];
    const float* ds0_m   = (const float*)d_in[5];
    const float* ds0_v   = (const float*)d_in[6];
    const float* ds1_dw  = (const float*)d_in[7];
    const float* ds1_pw  = (const float*)d_in[8];
    const float* ds1_g   = (const float*)d_in[9];
    const float* ds1_b   = (const float*)d_in[10];
    const float* ds1_m   = (const float*)d_in[11];
    const float* ds1_v   = (const float*)d_in[12];
    const float* ds2_dw  = (const float*)d_in[13];
    const float* ds2_pw  = (const float*)d_in[14];
    const float* ds2_g   = (const float*)d_in[15];
    const float* ds2_b   = (const float*)d_in[16];
    const float* ds2_m   = (const float*)d_in[17];
    const float* ds2_v   = (const float*)d_in[18];
    const float* qproj_w = (const float*)d_in[19];
    const float* h1_w1   = (const float*)d_in[20];
    const float* h1_w2   = (const float*)d_in[21];
    const float* h1_b2   = (const float*)d_in[22];
    const float* h2_w1   = (const float*)d_in[23];
    const float* h2_w2   = (const float*)d_in[24];
    const float* h2_b2   = (const float*)d_in[25];
    const float* r_w1    = (const float*)d_in[26];
    const float* r_b1    = (const float*)d_in[27];
    const float* r_w2    = (const float*)d_in[28];
    const float* r_b2    = (const float*)d_in[29];
    const float* final_w = (const float*)d_in[30];
    float* out = (float*)d_out;

    float *z0, *q, *z1, *z2, *y1, *y2, *part, *alpha;
    cudaGetSymbolAddress((void**)&z0,    g_z0);
    cudaGetSymbolAddress((void**)&q,     g_q);
    cudaGetSymbolAddress((void**)&z1,    g_z1);
    cudaGetSymbolAddress((void**)&z2,    g_z2);
    cudaGetSymbolAddress((void**)&y1,    g_y1);
    cudaGetSymbolAddress((void**)&y2,    g_y2);
    cudaGetSymbolAddress((void**)&part,  g_part);
    cudaGetSymbolAddress((void**)&alpha, g_alpha);

    ds_fat_kernel<<<1344, 256>>>(x,
        ds0_dw, ds0_pw, ds0_g, ds0_b, ds0_m, ds0_v,
        ds1_dw, ds1_pw, ds1_g, ds1_b, ds1_m, ds1_v,
        ds2_dw, ds2_pw, ds2_g, ds2_b, ds2_m, ds2_v,
        qproj_w, z0, q, z1, z2);

    head_fat_kernel<<<512, 256>>>(q, z1, z2,
        h1_w1, h1_w2, h1_b2, h2_w1, h2_w2, h2_b2, y1, y2);

    reduce_kernel<<<dim3(8,128,3), 256>>>(z0, y1, y2, part);
    alpha_kernel<<<1, 128>>>(part, r_w1, r_b1, r_w2, r_b2, alpha);
    final_kernel<<<dim3(256,4), 256>>>(x, z0, y1, y2, final_w, alpha, out);
}